// round 3
// baseline (speedup 1.0000x reference)
#include <cuda_runtime.h>
#include <math.h>

#define SLEN 1024
#define BSZ  32
#define IND  512
#define NH   8
#define HD   64
#define NQKVB 1544   /* 8*(3*64+1) */
#define ROWS 32768   /* SLEN*BSZ */

// ---------------- scratch (static device globals; no allocs allowed) ----------------
// g_qkvb: slow-net output; act_kernel normalizes q,k IN PLACE (v untouched, beta separate)
__device__ float g_qkvb[(size_t)ROWS * NQKVB]; // [row][h][{q(64),k(64),v(64),beta(1)}]
__device__ float g_beta[ROWS * NH];            // sigmoid(beta)
__device__ float g_o[(size_t)ROWS * 512];      // scan outputs  [t][b][h][d]
__device__ float g_mu[ROWS];
__device__ float g_rs[ROWS];

// ---------------- LN stats: one warp per row ----------------
__global__ __launch_bounds__(256) void ln_stats_kernel(const float* __restrict__ x) {
    int warp = threadIdx.x >> 5, lane = threadIdx.x & 31;
    int row = blockIdx.x * 8 + warp;
    const float4* xr = (const float4*)(x + (size_t)row * 512);
    float s = 0.f, s2 = 0.f;
#pragma unroll
    for (int r = 0; r < 4; r++) {
        float4 v = xr[lane + 32 * r];
        s  += (v.x + v.y) + (v.z + v.w);
        s2 += (v.x * v.x + v.y * v.y) + (v.z * v.z + v.w * v.w);
    }
#pragma unroll
    for (int off = 16; off > 0; off >>= 1) {
        s  += __shfl_xor_sync(0xffffffffu, s,  off);
        s2 += __shfl_xor_sync(0xffffffffu, s2, off);
    }
    if (lane == 0) {
        float m   = s * (1.f / 512.f);
        float var = s2 * (1.f / 512.f) - m * m;
        g_mu[row] = m;
        g_rs[row] = rsqrtf(var + 1e-5f);
    }
}

// ---------------- generic fp32 tiled GEMM: C = op(A) @ B (+res) ----------------
// BM=128, BN=128, BK=8, 256 threads, 8x8 microtile. LN applied to A on load if LN.
template <bool LN, bool RES>
__device__ __forceinline__ void sgemm_body(
    const float* __restrict__ A, const float* __restrict__ B, float* __restrict__ C,
    int M, int N, int K,
    const float* __restrict__ mu, const float* __restrict__ rsig,
    const float* __restrict__ gamma, const float* __restrict__ lnb,
    const float* __restrict__ res)
{
    __shared__ float As[8][132];
    __shared__ float Bs[8][128];
    int tid = threadIdx.x;
    int bm = blockIdx.y * 128, bn = blockIdx.x * 128;

    int arow = tid >> 1, acol = (tid & 1) * 4;
    int brow = tid >> 5, bcol = (tid & 31) * 4;
    const float* Aptr = A + (size_t)(bm + arow) * K + acol;
    const float* Bptr = B + (size_t)brow * N + bn + bcol;
    bool bnin = (bn + bcol) < N;

    float amu = 0.f, ars = 1.f;
    if (LN) { amu = mu[bm + arow]; ars = rsig[bm + arow]; }

    int tx = tid & 15, ty = tid >> 4;
    float acc[8][8];
#pragma unroll
    for (int i = 0; i < 8; i++)
#pragma unroll
        for (int j = 0; j < 8; j++) acc[i][j] = 0.f;

    float4 aReg = *(const float4*)Aptr;
    float4 bReg = bnin ? *(const float4*)Bptr : make_float4(0.f, 0.f, 0.f, 0.f);

    int KT = K >> 3;
    for (int kt = 0; kt < KT; kt++) {
        float4 av = aReg;
        if (LN) {
            float4 g  = *(const float4*)(gamma + kt * 8 + acol);
            float4 bb = *(const float4*)(lnb   + kt * 8 + acol);
            av.x = (av.x - amu) * ars * g.x + bb.x;
            av.y = (av.y - amu) * ars * g.y + bb.y;
            av.z = (av.z - amu) * ars * g.z + bb.z;
            av.w = (av.w - amu) * ars * g.w + bb.w;
        }
        __syncthreads();  // prior compute done before smem overwrite
        As[acol + 0][arow] = av.x;
        As[acol + 1][arow] = av.y;
        As[acol + 2][arow] = av.z;
        As[acol + 3][arow] = av.w;
        *(float4*)&Bs[brow][bcol] = bReg;
        __syncthreads();
        if (kt + 1 < KT) {
            aReg = *(const float4*)(Aptr + (kt + 1) * 8);
            bReg = bnin ? *(const float4*)(Bptr + (size_t)(kt + 1) * 8 * N)
                        : make_float4(0.f, 0.f, 0.f, 0.f);
        }
#pragma unroll
        for (int kk = 0; kk < 8; kk++) {
            float4 a0 = *(const float4*)&As[kk][ty * 8];
            float4 a1 = *(const float4*)&As[kk][ty * 8 + 4];
            float4 b0 = *(const float4*)&Bs[kk][tx * 8];
            float4 b1 = *(const float4*)&Bs[kk][tx * 8 + 4];
            float ar[8] = {a0.x, a0.y, a0.z, a0.w, a1.x, a1.y, a1.z, a1.w};
            float br[8] = {b0.x, b0.y, b0.z, b0.w, b1.x, b1.y, b1.z, b1.w};
#pragma unroll
            for (int i = 0; i < 8; i++)
#pragma unroll
                for (int j = 0; j < 8; j++)
                    acc[i][j] = fmaf(ar[i], br[j], acc[i][j]);
        }
    }

#pragma unroll
    for (int i = 0; i < 8; i++) {
        int r = bm + ty * 8 + i;
#pragma unroll
        for (int j = 0; j < 8; j += 4) {
            int c = bn + tx * 8 + j;
            if (c < N) {
                float4 v = make_float4(acc[i][j], acc[i][j + 1], acc[i][j + 2], acc[i][j + 3]);
                if (RES) {
                    float4 rv = *(const float4*)(res + (size_t)r * N + c);
                    v.x += rv.x; v.y += rv.y; v.z += rv.z; v.w += rv.w;
                }
                *(float4*)(C + (size_t)r * N + c) = v;
            }
        }
    }
}

__global__ __launch_bounds__(256, 2) void gemm1_kernel(
    const float* __restrict__ x, const float* __restrict__ wslow,
    const float* __restrict__ gamma, const float* __restrict__ lnb)
{
    sgemm_body<true, false>(x, wslow, g_qkvb, ROWS, NQKVB, IND,
                            g_mu, g_rs, gamma, lnb, nullptr);
}

__global__ __launch_bounds__(256, 2) void gemm2_kernel(
    const float* __restrict__ wout, const float* __restrict__ x, float* __restrict__ out)
{
    sgemm_body<false, true>(g_o, wout, out, ROWS, IND, 512,
                            nullptr, nullptr, nullptr, nullptr, x);
}

// ---------------- activations: warp per (row, head), normalize q/k IN PLACE --------
__global__ __launch_bounds__(256) void act_kernel() {
    int row = blockIdx.x;
    int h = threadIdx.x >> 5, lane = threadIdx.x & 31;
    float* base = g_qkvb + (size_t)row * NQKVB + h * 193;

    // q (elements 0..63)
    {
        float a0 = base[lane], a1 = base[lane + 32];
        float e0 = a0 > 0.f ? a0 + 1.f : expf(a0);
        float e1 = a1 > 0.f ? a1 + 1.f : expf(a1);
        float s = e0 + e1;
#pragma unroll
        for (int off = 16; off > 0; off >>= 1) s += __shfl_xor_sync(0xffffffffu, s, off);
        float inv = 1.f / s;
        base[lane]      = e0 * inv;
        base[lane + 32] = e1 * inv;
    }
    // k (elements 64..127)
    {
        float a0 = base[64 + lane], a1 = base[64 + lane + 32];
        float e0 = a0 > 0.f ? a0 + 1.f : expf(a0);
        float e1 = a1 > 0.f ? a1 + 1.f : expf(a1);
        float s = e0 + e1;
#pragma unroll
        for (int off = 16; off > 0; off >>= 1) s += __shfl_xor_sync(0xffffffffu, s, off);
        float inv = 1.f / s;
        base[64 + lane]      = e0 * inv;
        base[64 + lane + 32] = e1 * inv;
    }
    if (lane == 0) g_beta[row * NH + h] = 1.f / (1.f + expf(-base[192]));
}

// ---------------- delta-rule scan: one block per (b,h), W row per thread ----------------
__global__ __launch_bounds__(64) void scan_kernel() {
    int bh = blockIdx.x;
    int b = bh >> 3, h = bh & 7;
    int i = threadIdx.x;  // W row

    float w[64];
#pragma unroll
    for (int j = 0; j < 64; j++) w[j] = 0.f;

    __shared__ float4 sk[2][16], sq[2][16], sv[2][16];
    __shared__ float sb[2];

    // preload t = 0
    {
        const float* base = g_qkvb + (size_t)b * NQKVB + h * 193;
        ((float*)sq[0])[i] = base[i];
        ((float*)sk[0])[i] = base[64 + i];
        ((float*)sv[0])[i] = base[128 + i];
        if (i == 0) sb[0] = g_beta[b * NH + h];
    }
    __syncthreads();

    for (int t = 0; t < SLEN; t++) {
        int cur = t & 1;
        // prefetch t+1 while computing t
        float pk = 0.f, pq = 0.f, pv = 0.f, pb = 0.f;
        if (t + 1 < SLEN) {
            const float* nb = g_qkvb + (size_t)((t + 1) * BSZ + b) * NQKVB + h * 193;
            pq = nb[i];
            pk = nb[64 + i];
            pv = nb[128 + i];
            if (i == 0) pb = g_beta[((t + 1) * BSZ + b) * NH + h];
        }

        float beta = sb[cur];
        float vi = ((const float*)sv[cur])[i];

        // v_old_i = W_row_i . k
        float vo0 = 0.f, vo1 = 0.f, vo2 = 0.f, vo3 = 0.f;
#pragma unroll
        for (int j = 0; j < 16; j++) {
            float4 kv = sk[cur][j];
            vo0 = fmaf(w[4 * j + 0], kv.x, vo0);
            vo1 = fmaf(w[4 * j + 1], kv.y, vo1);
            vo2 = fmaf(w[4 * j + 2], kv.z, vo2);
            vo3 = fmaf(w[4 * j + 3], kv.w, vo3);
        }
        float upd = beta * (vi - ((vo0 + vo1) + (vo2 + vo3)));

        // W_row_i += upd * k ; o_i = W_row_i(new) . q
        float o0 = 0.f, o1 = 0.f, o2 = 0.f, o3 = 0.f;
#pragma unroll
        for (int j = 0; j < 16; j++) {
            float4 kv = sk[cur][j];
            float4 qv = sq[cur][j];
            w[4 * j + 0] = fmaf(upd, kv.x, w[4 * j + 0]); o0 = fmaf(w[4 * j + 0], qv.x, o0);
            w[4 * j + 1] = fmaf(upd, kv.y, w[4 * j + 1]); o1 = fmaf(w[4 * j + 1], qv.y, o1);
            w[4 * j + 2] = fmaf(upd, kv.z, w[4 * j + 2]); o2 = fmaf(w[4 * j + 2], qv.z, o2);
            w[4 * j + 3] = fmaf(upd, kv.w, w[4 * j + 3]); o3 = fmaf(w[4 * j + 3], qv.w, o3);
        }
        g_o[((size_t)(t * BSZ + b)) * 512 + h * 64 + i] = (o0 + o1) + (o2 + o3);

        if (t + 1 < SLEN) {
            int nxt = cur ^ 1;
            ((float*)sk[nxt])[i] = pk;
            ((float*)sq[nxt])[i] = pq;
            ((float*)sv[nxt])[i] = pv;
            if (i == 0) sb[nxt] = pb;
        }
        __syncthreads();
    }
}

// ---------------- launch ----------------
extern "C" void kernel_launch(void* const* d_in, const int* in_sizes, int n_in,
                              void* d_out, int out_size) {
    const float* x     = (const float*)d_in[0];
    const float* gamma = (const float*)d_in[1];
    const float* lnb   = (const float*)d_in[2];
    const float* wslow = (const float*)d_in[3];
    const float* wout  = (const float*)d_in[4];
    float* out = (float*)d_out;

    ln_stats_kernel<<<ROWS / 8, 256>>>(x);
    gemm1_kernel<<<dim3((NQKVB + 127) / 128, ROWS / 128), 256>>>(x, wslow, gamma, lnb);
    act_kernel<<<ROWS, 256>>>();
    scan_kernel<<<BSZ * NH, 64>>>();
    gemm2_kernel<<<dim3(512 / 128, ROWS / 128), 256>>>(wout, x, out);
}

// round 6
// speedup vs baseline: 1.7047x; 1.7047x over previous
#include <cuda_runtime.h>
#include <cuda_bf16.h>
#include <cstdint>
#include <math.h>

#define SLEN 1024
#define BSZ  32
#define NH   8
#define NQKVB 1544   /* 8*(3*64+1) */
#define ROWS 32768   /* SLEN*BSZ */
#define NPAD1 1664   /* 13*128 */
#define NT1  13
#define NT2  4

typedef __nv_bfloat16 bf16;

// ------------------------------------------------------------------ scratch
__device__ float g_qkvb[(size_t)ROWS * NQKVB];
__device__ float g_beta[ROWS * NH];
__device__ __align__(256) bf16 g_A1h[(size_t)ROWS * 512];
__device__ __align__(256) bf16 g_A1l[(size_t)ROWS * 512];
__device__ __align__(256) bf16 g_A2h[(size_t)ROWS * 512];
__device__ __align__(256) bf16 g_A2l[(size_t)ROWS * 512];
__device__ __align__(256) bf16 g_B1h[(size_t)NPAD1 * 512];
__device__ __align__(256) bf16 g_B1l[(size_t)NPAD1 * 512];
__device__ __align__(256) bf16 g_B2h[(size_t)512 * 512];
__device__ __align__(256) bf16 g_B2l[(size_t)512 * 512];

// ------------------------------------------------------------------ helpers
__device__ __forceinline__ uint32_t smem_u32(const void* p) {
    uint32_t a;
    asm("{ .reg .u64 t; cvta.to.shared.u64 t, %1; cvt.u32.u64 %0, t; }" : "=r"(a) : "l"(p));
    return a;
}
__device__ __forceinline__ void cp_async16(uint32_t dst, const void* src) {
    asm volatile("cp.async.cg.shared.global [%0], [%1], 16;" :: "r"(dst), "l"(src) : "memory");
}
__device__ __forceinline__ void ldmatrix_x4(uint32_t* r, uint32_t addr) {
    asm volatile("ldmatrix.sync.aligned.m8n8.x4.shared.b16 {%0,%1,%2,%3}, [%4];"
                 : "=r"(r[0]), "=r"(r[1]), "=r"(r[2]), "=r"(r[3]) : "r"(addr));
}
__device__ __forceinline__ void mma_bf16(float* c, const uint32_t* a, uint32_t b0, uint32_t b1) {
    asm volatile(
        "mma.sync.aligned.m16n8k16.row.col.f32.bf16.bf16.f32 "
        "{%0,%1,%2,%3}, {%4,%5,%6,%7}, {%8,%9}, {%0,%1,%2,%3};"
        : "+f"(c[0]), "+f"(c[1]), "+f"(c[2]), "+f"(c[3])
        : "r"(a[0]), "r"(a[1]), "r"(a[2]), "r"(a[3]), "r"(b0), "r"(b1));
}

// ------------------------------------------------------------------ prep X: fused LN + bf16 split
__global__ __launch_bounds__(128) void prep_x_kernel(
    const float* __restrict__ x, const float* __restrict__ gamma, const float* __restrict__ lnb,
    bf16* __restrict__ Ah, bf16* __restrict__ Al)
{
    int row = blockIdx.x, tid = threadIdx.x;
    float4 v = *(const float4*)(x + (size_t)row * 512 + tid * 4);
    float s  = (v.x + v.y) + (v.z + v.w);
    float s2 = (v.x * v.x + v.y * v.y) + (v.z * v.z + v.w * v.w);
#pragma unroll
    for (int off = 16; off > 0; off >>= 1) {
        s  += __shfl_xor_sync(0xffffffffu, s,  off);
        s2 += __shfl_xor_sync(0xffffffffu, s2, off);
    }
    __shared__ float as_[4], aq_[4];
    int w = tid >> 5, l = tid & 31;
    if (l == 0) { as_[w] = s; aq_[w] = s2; }
    __syncthreads();
    float ts = (as_[0] + as_[1]) + (as_[2] + as_[3]);
    float tq = (aq_[0] + aq_[1]) + (aq_[2] + aq_[3]);
    float m  = ts * (1.f / 512.f);
    float ri = rsqrtf(tq * (1.f / 512.f) - m * m + 1e-5f);

    float4 g = *(const float4*)(gamma + tid * 4);
    float4 b = *(const float4*)(lnb   + tid * 4);
    float nx = (v.x - m) * ri * g.x + b.x;
    float ny = (v.y - m) * ri * g.y + b.y;
    float nz = (v.z - m) * ri * g.z + b.z;
    float nw = (v.w - m) * ri * g.w + b.w;

    __nv_bfloat162 h01 = __floats2bfloat162_rn(nx, ny);
    __nv_bfloat162 h23 = __floats2bfloat162_rn(nz, nw);
    __nv_bfloat162 l01 = __floats2bfloat162_rn(nx - __low2float(h01), ny - __high2float(h01));
    __nv_bfloat162 l23 = __floats2bfloat162_rn(nz - __low2float(h23), nw - __high2float(h23));
    size_t o = (size_t)row * 512 + tid * 4;
    *(__nv_bfloat162*)(Ah + o)     = h01;
    *(__nv_bfloat162*)(Ah + o + 2) = h23;
    *(__nv_bfloat162*)(Al + o)     = l01;
    *(__nv_bfloat162*)(Al + o + 2) = l23;
}

// ------------------------------------------------------------------ prep B: transpose [512][N] -> [Npad][512] + split
__global__ __launch_bounds__(256) void prep_b_kernel(
    const float* __restrict__ W, bf16* __restrict__ Bh, bf16* __restrict__ Bl, int N)
{
    __shared__ float t[32][33];
    int nt = blockIdx.x, kt = blockIdx.y;
    int tx = threadIdx.x & 31, ty = threadIdx.x >> 5;  // 32 x 8
#pragma unroll
    for (int r = 0; r < 4; r++) {
        int k = kt * 32 + ty + r * 8;
        int n = nt * 32 + tx;
        t[tx][ty + r * 8] = (n < N) ? W[(size_t)k * N + n] : 0.f;
    }
    __syncthreads();
#pragma unroll
    for (int r = 0; r < 4; r++) {
        int n = nt * 32 + ty + r * 8;
        int k = kt * 32 + tx;
        float v = t[ty + r * 8][tx];
        bf16 h = __float2bfloat16_rn(v);
        bf16 lo = __float2bfloat16_rn(v - __bfloat162float(h));
        Bh[(size_t)n * 512 + k] = h;
        Bl[(size_t)n * 512 + k] = lo;
    }
}

// ------------------------------------------------------------------ bf16 3-split tensor-core GEMM
// Block 128m x 128n, K=512 in 16 stages of 32. smem stage: Ah|Al|Bh|Bl, each 128 rows x 80B.
#define STG_ARR 10240
#define STG_SZ  40960
#define SMEM_DYN (2 * STG_SZ)

__global__ __launch_bounds__(256) void gemm_kernel(
    const bf16* __restrict__ Ah, const bf16* __restrict__ Al,
    const bf16* __restrict__ Bh, const bf16* __restrict__ Bl,
    float* __restrict__ C, const float* __restrict__ res, int N)
{
    extern __shared__ __align__(128) char smem[];
    uint32_t sb = smem_u32(smem);
    int tid = threadIdx.x, wid = tid >> 5, lane = tid & 31;
    int ntile = blockIdx.x, mtile = blockIdx.y;
    int wm = wid & 3, wn = wid >> 2;

    const bf16* srcs[4];
    srcs[0] = Ah + (size_t)mtile * 128 * 512;
    srcs[1] = Al + (size_t)mtile * 128 * 512;
    srcs[2] = Bh + (size_t)ntile * 128 * 512;
    srcs[3] = Bl + (size_t)ntile * 128 * 512;

    float c[2][8][4];
#pragma unroll
    for (int i = 0; i < 2; i++)
#pragma unroll
        for (int j = 0; j < 8; j++)
#pragma unroll
            for (int q = 0; q < 4; q++) c[i][j][q] = 0.f;

    // stage loader: 2048 16B-chunks, 8 per thread
    auto load_stage = [&](int kb, int buf) {
#pragma unroll
        for (int i = 0; i < 8; i++) {
            int id = tid + i * 256;
            int arr = id >> 9, rem = id & 511, row = rem >> 2, ch = rem & 3;
            const char* src = (const char*)(srcs[arr] + (size_t)row * 512 + kb * 32) + ch * 16;
            uint32_t dst = sb + buf * STG_SZ + arr * STG_ARR + row * 80 + ch * 16;
            cp_async16(dst, src);
        }
        asm volatile("cp.async.commit_group;" ::: "memory");
    };

    load_stage(0, 0);

    for (int kb = 0; kb < 16; kb++) {
        int buf = kb & 1;
        if (kb + 1 < 16) {
            load_stage(kb + 1, buf ^ 1);
            asm volatile("cp.async.wait_group 1;" ::: "memory");
        } else {
            asm volatile("cp.async.wait_group 0;" ::: "memory");
        }
        __syncthreads();

        uint32_t base = sb + buf * STG_SZ;
#pragma unroll
        for (int ks = 0; ks < 2; ks++) {
            uint32_t a_h[2][4], a_l[2][4], b_h[4][4], b_l[4][4];
#pragma unroll
            for (int mi = 0; mi < 2; mi++) {
                uint32_t row = wm * 32 + mi * 16 + (lane & 15);
                uint32_t col = ks * 32 + ((lane >> 4) & 1) * 16;
                uint32_t ad = base + row * 80 + col;
                ldmatrix_x4(a_h[mi], ad);
                ldmatrix_x4(a_l[mi], ad + STG_ARR);
            }
#pragma unroll
            for (int p = 0; p < 4; p++) {
                uint32_t row = wn * 64 + p * 16 + (lane & 7) + ((lane >> 4) & 1) * 8;
                uint32_t col = ks * 32 + ((lane >> 3) & 1) * 16;
                uint32_t bd = base + 2 * STG_ARR + row * 80 + col;
                ldmatrix_x4(b_h[p], bd);
                ldmatrix_x4(b_l[p], bd + STG_ARR);
            }
#pragma unroll
            for (int mi = 0; mi < 2; mi++)
#pragma unroll
                for (int p = 0; p < 4; p++)
#pragma unroll
                    for (int hf = 0; hf < 2; hf++) {
                        int nb = p * 2 + hf;
                        uint32_t bh0 = b_h[p][hf * 2], bh1 = b_h[p][hf * 2 + 1];
                        uint32_t bl0 = b_l[p][hf * 2], bl1 = b_l[p][hf * 2 + 1];
                        mma_bf16(c[mi][nb], a_h[mi], bh0, bh1);
                        mma_bf16(c[mi][nb], a_h[mi], bl0, bl1);
                        mma_bf16(c[mi][nb], a_l[mi], bh0, bh1);
                    }
        }
        __syncthreads();
    }

    // epilogue
    int grow = mtile * 128 + wm * 32;
    int gcol0 = ntile * 128 + wn * 64;
#pragma unroll
    for (int mi = 0; mi < 2; mi++) {
        int r0 = grow + mi * 16 + (lane >> 2);
#pragma unroll
        for (int nb = 0; nb < 8; nb++) {
            int col = gcol0 + nb * 8 + (lane & 3) * 2;
            if (col < N) {
                float2 v0 = make_float2(c[mi][nb][0], c[mi][nb][1]);
                float2 v1 = make_float2(c[mi][nb][2], c[mi][nb][3]);
                if (res) {
                    float2 q0 = *(const float2*)(res + (size_t)r0 * N + col);
                    float2 q1 = *(const float2*)(res + (size_t)(r0 + 8) * N + col);
                    v0.x += q0.x; v0.y += q0.y; v1.x += q1.x; v1.y += q1.y;
                }
                *(float2*)(C + (size_t)r0 * N + col)       = v0;
                *(float2*)(C + (size_t)(r0 + 8) * N + col) = v1;
            }
        }
    }
}

// ------------------------------------------------------------------ activations (in place)
__global__ __launch_bounds__(256) void act_kernel() {
    int row = blockIdx.x;
    int h = threadIdx.x >> 5, lane = threadIdx.x & 31;
    float* base = g_qkvb + (size_t)row * NQKVB + h * 193;
    {
        float a0 = base[lane], a1 = base[lane + 32];
        float e0 = a0 > 0.f ? a0 + 1.f : expf(a0);
        float e1 = a1 > 0.f ? a1 + 1.f : expf(a1);
        float s = e0 + e1;
#pragma unroll
        for (int off = 16; off > 0; off >>= 1) s += __shfl_xor_sync(0xffffffffu, s, off);
        float inv = 1.f / s;
        base[lane] = e0 * inv; base[lane + 32] = e1 * inv;
    }
    {
        float a0 = base[64 + lane], a1 = base[64 + lane + 32];
        float e0 = a0 > 0.f ? a0 + 1.f : expf(a0);
        float e1 = a1 > 0.f ? a1 + 1.f : expf(a1);
        float s = e0 + e1;
#pragma unroll
        for (int off = 16; off > 0; off >>= 1) s += __shfl_xor_sync(0xffffffffu, s, off);
        float inv = 1.f / s;
        base[64 + lane] = e0 * inv; base[64 + lane + 32] = e1 * inv;
    }
    if (lane == 0) g_beta[row * NH + h] = 1.f / (1.f + expf(-base[192]));
}

// ------------------------------------------------------------------ delta-rule scan: 128 thr, 2 per W row
// Writes bf16 hi/lo split of o directly (GEMM2's A operand).
__global__ __launch_bounds__(128) void scan_kernel() {
    int bh = blockIdx.x;
    int b = bh >> 3, h = bh & 7;
    int tid = threadIdx.x;
    int i = tid >> 1, half = tid & 1;

    float w[32];
#pragma unroll
    for (int j = 0; j < 32; j++) w[j] = 0.f;

    __shared__ float4 sq[2][16], sk[2][16], sv[2][16];
    __shared__ float sb_[2];

    {
        const float* b0 = g_qkvb + (size_t)b * NQKVB + h * 193;
        if (tid < 64) { ((float*)sq[0])[tid] = b0[tid]; ((float*)sv[0])[tid] = b0[128 + tid]; }
        else          { ((float*)sk[0])[tid - 64] = b0[64 + tid - 64]; }
        if (tid == 0) sb_[0] = g_beta[b * NH + h];
    }
    __syncthreads();

    for (int t = 0; t < SLEN; t++) {
        int cur = t & 1;
        float pq = 0.f, pk = 0.f, pv = 0.f, pb = 0.f;
        if (t + 1 < SLEN) {
            const float* nb = g_qkvb + (size_t)((t + 1) * BSZ + b) * NQKVB + h * 193;
            if (tid < 64) { pq = nb[tid]; pv = nb[128 + tid]; }
            else          { pk = nb[64 + tid - 64]; }
            if (tid == 0) pb = g_beta[((t + 1) * BSZ + b) * NH + h];
        }

        float beta = sb_[cur];
        float vi = ((const float*)sv[cur])[i];
        const float4* kk = &sk[cur][half * 8];
        const float4* qq = &sq[cur][half * 8];

        float vo0 = 0.f, vo1 = 0.f, vo2 = 0.f, vo3 = 0.f;
#pragma unroll
        for (int j = 0; j < 8; j++) {
            float4 kv = kk[j];
            vo0 = fmaf(w[4 * j + 0], kv.x, vo0);
            vo1 = fmaf(w[4 * j + 1], kv.y, vo1);
            vo2 = fmaf(w[4 * j + 2], kv.z, vo2);
            vo3 = fmaf(w[4 * j + 3], kv.w, vo3);
        }
        float vo = (vo0 + vo1) + (vo2 + vo3);
        vo += __shfl_xor_sync(0xffffffffu, vo, 1);
        float upd = beta * (vi - vo);

        float o0 = 0.f, o1 = 0.f, o2 = 0.f, o3 = 0.f;
#pragma unroll
        for (int j = 0; j < 8; j++) {
            float4 kv = kk[j];
            float4 qv = qq[j];
            w[4 * j + 0] = fmaf(upd, kv.x, w[4 * j + 0]); o0 = fmaf(w[4 * j + 0], qv.x, o0);
            w[4 * j + 1] = fmaf(upd, kv.y, w[4 * j + 1]); o1 = fmaf(w[4 * j + 1], qv.y, o1);
            w[4 * j + 2] = fmaf(upd, kv.z, w[4 * j + 2]); o2 = fmaf(w[4 * j + 2], qv.z, o2);
            w[4 * j + 3] = fmaf(upd, kv.w, w[4 * j + 3]); o3 = fmaf(w[4 * j + 3], qv.w, o3);
        }
        float o = (o0 + o1) + (o2 + o3);
        o += __shfl_xor_sync(0xffffffffu, o, 1);
        if (half == 0) {
            size_t idx = ((size_t)(t * BSZ + b)) * 512 + h * 64 + i;
            bf16 hv = __float2bfloat16_rn(o);
            g_A2h[idx] = hv;
            g_A2l[idx] = __float2bfloat16_rn(o - __bfloat162float(hv));
        }

        if (t + 1 < SLEN) {
            int nxt = cur ^ 1;
            if (tid < 64) { ((float*)sq[nxt])[tid] = pq; ((float*)sv[nxt])[tid] = pv; }
            else          { ((float*)sk[nxt])[tid - 64] = pk; }
            if (tid == 0) sb_[nxt] = pb;
        }
        __syncthreads();
    }
}

// ------------------------------------------------------------------ launch
extern "C" void kernel_launch(void* const* d_in, const int* in_sizes, int n_in,
                              void* d_out, int out_size) {
    const float* x     = (const float*)d_in[0];
    const float* gamma = (const float*)d_in[1];
    const float* lnb   = (const float*)d_in[2];
    const float* wslow = (const float*)d_in[3];
    const float* wout  = (const float*)d_in[4];
    float* out = (float*)d_out;

    cudaFuncSetAttribute(gemm_kernel, cudaFuncAttributeMaxDynamicSharedMemorySize, SMEM_DYN);

    bf16 *A1h, *A1l, *A2h, *A2l, *B1h, *B1l, *B2h, *B2l;
    cudaGetSymbolAddress((void**)&A1h, g_A1h);
    cudaGetSymbolAddress((void**)&A1l, g_A1l);
    cudaGetSymbolAddress((void**)&A2h, g_A2h);
    cudaGetSymbolAddress((void**)&A2l, g_A2l);
    cudaGetSymbolAddress((void**)&B1h, g_B1h);
    cudaGetSymbolAddress((void**)&B1l, g_B1l);
    cudaGetSymbolAddress((void**)&B2h, g_B2h);
    cudaGetSymbolAddress((void**)&B2l, g_B2l);
    float* qkvb;
    cudaGetSymbolAddress((void**)&qkvb, g_qkvb);

    prep_x_kernel<<<ROWS, 128>>>(x, gamma, lnb, A1h, A1l);
    prep_b_kernel<<<dim3(NPAD1 / 32, 16), 256>>>(wslow, B1h, B1l, NQKVB);
    prep_b_kernel<<<dim3(512 / 32, 16), 256>>>(wout, B2h, B2l, 512);
    gemm_kernel<<<dim3(NT1, 256), 256, SMEM_DYN>>>(A1h, A1l, B1h, B1l, qkvb, nullptr, NQKVB);
    act_kernel<<<ROWS, 256>>>();
    scan_kernel<<<BSZ * NH, 128>>>();
    gemm_kernel<<<dim3(NT2, 256), 256, SMEM_DYN>>>(A2h, A2l, B2h, B2l, out, x, 512);
}

// round 7
// speedup vs baseline: 1.7562x; 1.0302x over previous
#include <cuda_runtime.h>
#include <cuda_bf16.h>
#include <cstdint>
#include <math.h>

#define SLEN 1024
#define BSZ  32
#define NH   8
#define NQKVB 1544   /* 8*(3*64+1) */
#define ROWS 32768   /* SLEN*BSZ */
#define NPAD1 1664   /* 13*128 */
#define NT1  13
#define NT2  4

typedef __nv_bfloat16 bf16;

// ------------------------------------------------------------------ scratch
__device__ float g_qkvb[(size_t)ROWS * NQKVB];
__device__ __align__(256) bf16 g_A1h[(size_t)ROWS * 512];
__device__ __align__(256) bf16 g_A1l[(size_t)ROWS * 512];
__device__ __align__(256) bf16 g_A2h[(size_t)ROWS * 512];
__device__ __align__(256) bf16 g_A2l[(size_t)ROWS * 512];
__device__ __align__(256) bf16 g_B1h[(size_t)NPAD1 * 512];
__device__ __align__(256) bf16 g_B1l[(size_t)NPAD1 * 512];
__device__ __align__(256) bf16 g_B2h[(size_t)512 * 512];
__device__ __align__(256) bf16 g_B2l[(size_t)512 * 512];

// ------------------------------------------------------------------ helpers
__device__ __forceinline__ uint32_t smem_u32(const void* p) {
    uint32_t a;
    asm("{ .reg .u64 t; cvta.to.shared.u64 t, %1; cvt.u32.u64 %0, t; }" : "=r"(a) : "l"(p));
    return a;
}
__device__ __forceinline__ void cp_async16(uint32_t dst, const void* src) {
    asm volatile("cp.async.cg.shared.global [%0], [%1], 16;" :: "r"(dst), "l"(src) : "memory");
}
__device__ __forceinline__ void cp_async4(uint32_t dst, const void* src) {
    asm volatile("cp.async.ca.shared.global [%0], [%1], 4;" :: "r"(dst), "l"(src) : "memory");
}
__device__ __forceinline__ void ldmatrix_x4(uint32_t* r, uint32_t addr) {
    asm volatile("ldmatrix.sync.aligned.m8n8.x4.shared.b16 {%0,%1,%2,%3}, [%4];"
                 : "=r"(r[0]), "=r"(r[1]), "=r"(r[2]), "=r"(r[3]) : "r"(addr));
}
__device__ __forceinline__ void mma_bf16(float* c, const uint32_t* a, uint32_t b0, uint32_t b1) {
    asm volatile(
        "mma.sync.aligned.m16n8k16.row.col.f32.bf16.bf16.f32 "
        "{%0,%1,%2,%3}, {%4,%5,%6,%7}, {%8,%9}, {%0,%1,%2,%3};"
        : "+f"(c[0]), "+f"(c[1]), "+f"(c[2]), "+f"(c[3])
        : "r"(a[0]), "r"(a[1]), "r"(a[2]), "r"(a[3]), "r"(b0), "r"(b1));
}

// ------------------------------------------------------------------ prep X: fused LN + bf16 split
__global__ __launch_bounds__(128) void prep_x_kernel(
    const float* __restrict__ x, const float* __restrict__ gamma, const float* __restrict__ lnb,
    bf16* __restrict__ Ah, bf16* __restrict__ Al)
{
    int row = blockIdx.x, tid = threadIdx.x;
    float4 v = *(const float4*)(x + (size_t)row * 512 + tid * 4);
    float s  = (v.x + v.y) + (v.z + v.w);
    float s2 = (v.x * v.x + v.y * v.y) + (v.z * v.z + v.w * v.w);
#pragma unroll
    for (int off = 16; off > 0; off >>= 1) {
        s  += __shfl_xor_sync(0xffffffffu, s,  off);
        s2 += __shfl_xor_sync(0xffffffffu, s2, off);
    }
    __shared__ float as_[4], aq_[4];
    int w = tid >> 5, l = tid & 31;
    if (l == 0) { as_[w] = s; aq_[w] = s2; }
    __syncthreads();
    float ts = (as_[0] + as_[1]) + (as_[2] + as_[3]);
    float tq = (aq_[0] + aq_[1]) + (aq_[2] + aq_[3]);
    float m  = ts * (1.f / 512.f);
    float ri = rsqrtf(tq * (1.f / 512.f) - m * m + 1e-5f);

    float4 g = *(const float4*)(gamma + tid * 4);
    float4 b = *(const float4*)(lnb   + tid * 4);
    float nx = (v.x - m) * ri * g.x + b.x;
    float ny = (v.y - m) * ri * g.y + b.y;
    float nz = (v.z - m) * ri * g.z + b.z;
    float nw = (v.w - m) * ri * g.w + b.w;

    __nv_bfloat162 h01 = __floats2bfloat162_rn(nx, ny);
    __nv_bfloat162 h23 = __floats2bfloat162_rn(nz, nw);
    __nv_bfloat162 l01 = __floats2bfloat162_rn(nx - __low2float(h01), ny - __high2float(h01));
    __nv_bfloat162 l23 = __floats2bfloat162_rn(nz - __low2float(h23), nw - __high2float(h23));
    size_t o = (size_t)row * 512 + tid * 4;
    *(__nv_bfloat162*)(Ah + o)     = h01;
    *(__nv_bfloat162*)(Ah + o + 2) = h23;
    *(__nv_bfloat162*)(Al + o)     = l01;
    *(__nv_bfloat162*)(Al + o + 2) = l23;
}

// ------------------------------------------------------------------ prep B: transpose [512][N] -> [Npad][512] + split
__global__ __launch_bounds__(256) void prep_b_kernel(
    const float* __restrict__ W, bf16* __restrict__ Bh, bf16* __restrict__ Bl, int N)
{
    __shared__ float t[32][33];
    int nt = blockIdx.x, kt = blockIdx.y;
    int tx = threadIdx.x & 31, ty = threadIdx.x >> 5;  // 32 x 8
#pragma unroll
    for (int r = 0; r < 4; r++) {
        int k = kt * 32 + ty + r * 8;
        int n = nt * 32 + tx;
        t[tx][ty + r * 8] = (n < N) ? W[(size_t)k * N + n] : 0.f;
    }
    __syncthreads();
#pragma unroll
    for (int r = 0; r < 4; r++) {
        int n = nt * 32 + ty + r * 8;
        int k = kt * 32 + tx;
        float v = t[ty + r * 8][tx];
        bf16 h = __float2bfloat16_rn(v);
        bf16 lo = __float2bfloat16_rn(v - __bfloat162float(h));
        Bh[(size_t)n * 512 + k] = h;
        Bl[(size_t)n * 512 + k] = lo;
    }
}

// ------------------------------------------------------------------ bf16 3-split tensor-core GEMM
#define STG_ARR 10240
#define STG_SZ  40960
#define SMEM_DYN (2 * STG_SZ)

__global__ __launch_bounds__(256) void gemm_kernel(
    const bf16* __restrict__ Ah, const bf16* __restrict__ Al,
    const bf16* __restrict__ Bh, const bf16* __restrict__ Bl,
    float* __restrict__ C, const float* __restrict__ res, int N)
{
    extern __shared__ __align__(128) char smem[];
    uint32_t sb = smem_u32(smem);
    int tid = threadIdx.x, wid = tid >> 5, lane = tid & 31;
    int ntile = blockIdx.x, mtile = blockIdx.y;
    int wm = wid & 3, wn = wid >> 2;

    const bf16* srcs[4];
    srcs[0] = Ah + (size_t)mtile * 128 * 512;
    srcs[1] = Al + (size_t)mtile * 128 * 512;
    srcs[2] = Bh + (size_t)ntile * 128 * 512;
    srcs[3] = Bl + (size_t)ntile * 128 * 512;

    float c[2][8][4];
#pragma unroll
    for (int i = 0; i < 2; i++)
#pragma unroll
        for (int j = 0; j < 8; j++)
#pragma unroll
            for (int q = 0; q < 4; q++) c[i][j][q] = 0.f;

    auto load_stage = [&](int kb, int buf) {
#pragma unroll
        for (int i = 0; i < 8; i++) {
            int id = tid + i * 256;
            int arr = id >> 9, rem = id & 511, row = rem >> 2, ch = rem & 3;
            const char* src = (const char*)(srcs[arr] + (size_t)row * 512 + kb * 32) + ch * 16;
            uint32_t dst = sb + buf * STG_SZ + arr * STG_ARR + row * 80 + ch * 16;
            cp_async16(dst, src);
        }
        asm volatile("cp.async.commit_group;" ::: "memory");
    };

    load_stage(0, 0);

    for (int kb = 0; kb < 16; kb++) {
        int buf = kb & 1;
        if (kb + 1 < 16) {
            load_stage(kb + 1, buf ^ 1);
            asm volatile("cp.async.wait_group 1;" ::: "memory");
        } else {
            asm volatile("cp.async.wait_group 0;" ::: "memory");
        }
        __syncthreads();

        uint32_t base = sb + buf * STG_SZ;
#pragma unroll
        for (int ks = 0; ks < 2; ks++) {
            uint32_t a_h[2][4], a_l[2][4], b_h[4][4], b_l[4][4];
#pragma unroll
            for (int mi = 0; mi < 2; mi++) {
                uint32_t row = wm * 32 + mi * 16 + (lane & 15);
                uint32_t col = ks * 32 + ((lane >> 4) & 1) * 16;
                uint32_t ad = base + row * 80 + col;
                ldmatrix_x4(a_h[mi], ad);
                ldmatrix_x4(a_l[mi], ad + STG_ARR);
            }
#pragma unroll
            for (int p = 0; p < 4; p++) {
                uint32_t row = wn * 64 + p * 16 + (lane & 7) + ((lane >> 4) & 1) * 8;
                uint32_t col = ks * 32 + ((lane >> 3) & 1) * 16;
                uint32_t bd = base + 2 * STG_ARR + row * 80 + col;
                ldmatrix_x4(b_h[p], bd);
                ldmatrix_x4(b_l[p], bd + STG_ARR);
            }
#pragma unroll
            for (int mi = 0; mi < 2; mi++)
#pragma unroll
                for (int p = 0; p < 4; p++)
#pragma unroll
                    for (int hf = 0; hf < 2; hf++) {
                        int nb = p * 2 + hf;
                        uint32_t bh0 = b_h[p][hf * 2], bh1 = b_h[p][hf * 2 + 1];
                        uint32_t bl0 = b_l[p][hf * 2], bl1 = b_l[p][hf * 2 + 1];
                        mma_bf16(c[mi][nb], a_h[mi], bh0, bh1);
                        mma_bf16(c[mi][nb], a_h[mi], bl0, bl1);
                        mma_bf16(c[mi][nb], a_l[mi], bh0, bh1);
                    }
        }
        __syncthreads();
    }

    int grow = mtile * 128 + wm * 32;
    int gcol0 = ntile * 128 + wn * 64;
#pragma unroll
    for (int mi = 0; mi < 2; mi++) {
        int r0 = grow + mi * 16 + (lane >> 2);
#pragma unroll
        for (int nb = 0; nb < 8; nb++) {
            int col = gcol0 + nb * 8 + (lane & 3) * 2;
            if (col < N) {
                float2 v0 = make_float2(c[mi][nb][0], c[mi][nb][1]);
                float2 v1 = make_float2(c[mi][nb][2], c[mi][nb][3]);
                if (res) {
                    float2 q0 = *(const float2*)(res + (size_t)r0 * N + col);
                    float2 q1 = *(const float2*)(res + (size_t)(r0 + 8) * N + col);
                    v0.x += q0.x; v0.y += q0.y; v1.x += q1.x; v1.y += q1.y;
                }
                *(float2*)(C + (size_t)r0 * N + col)       = v0;
                *(float2*)(C + (size_t)(r0 + 8) * N + col) = v1;
            }
        }
    }
}

// ------------------------------------------------------------------ activations (in place; sigmoid(beta) stored in place too)
__global__ __launch_bounds__(256) void act_kernel() {
    int row = blockIdx.x;
    int h = threadIdx.x >> 5, lane = threadIdx.x & 31;
    float* base = g_qkvb + (size_t)row * NQKVB + h * 193;
    {
        float a0 = base[lane], a1 = base[lane + 32];
        float e0 = a0 > 0.f ? a0 + 1.f : expf(a0);
        float e1 = a1 > 0.f ? a1 + 1.f : expf(a1);
        float s = e0 + e1;
#pragma unroll
        for (int off = 16; off > 0; off >>= 1) s += __shfl_xor_sync(0xffffffffu, s, off);
        float inv = 1.f / s;
        base[lane] = e0 * inv; base[lane + 32] = e1 * inv;
    }
    {
        float a0 = base[64 + lane], a1 = base[64 + lane + 32];
        float e0 = a0 > 0.f ? a0 + 1.f : expf(a0);
        float e1 = a1 > 0.f ? a1 + 1.f : expf(a1);
        float s = e0 + e1;
#pragma unroll
        for (int off = 16; off > 0; off >>= 1) s += __shfl_xor_sync(0xffffffffu, s, off);
        float inv = 1.f / s;
        base[64 + lane] = e0 * inv; base[64 + lane + 32] = e1 * inv;
    }
    if (lane == 0) base[192] = 1.f / (1.f + expf(-base[192]));
}

// ------------------------------------------------------------------ delta-rule scan
// 256 threads/block: 4 threads per W row (16 cols each). cp.async ring-4 prefetch,
// 2 steps ahead; one __syncthreads per step. Emits bf16 hi/lo of o (GEMM2's A).
__global__ __launch_bounds__(256) void scan_kernel() {
    int bh = blockIdx.x;
    int b = bh >> 3, h = bh & 7;
    int tid = threadIdx.x;
    int i = tid >> 2;        // W row 0..63
    int qd = tid & 3;        // quarter within row
    int c0 = qd * 16;

    float w[16];
#pragma unroll
    for (int j = 0; j < 16; j++) w[j] = 0.f;

    __shared__ float s_qkv[4][192];  // [buf][ q(64) | k(64) | v(64) ]
    __shared__ float s_b[4];

    const float* gbase = g_qkvb + (size_t)b * NQKVB + h * 193;
    const size_t tstride = (size_t)BSZ * NQKVB;

    uint32_t s_qkv_a = smem_u32(&s_qkv[0][0]);
    uint32_t s_b_a   = smem_u32(&s_b[0]);

    // preload t = 0, 1 (one commit group each)
#pragma unroll
    for (int t = 0; t < 2; t++) {
        const float* src = gbase + t * tstride;
        if (tid < 192)       cp_async4(s_qkv_a + (t * 192 + tid) * 4, src + tid);
        else if (tid == 192) cp_async4(s_b_a + t * 4, src + 192);
        asm volatile("cp.async.commit_group;" ::: "memory");
    }

    for (int t = 0; t < SLEN; t++) {
        int cur = t & 3;
        // prefetch t+2 into buffer (t+2)&3 (last read at step t-2; safe after prior barrier)
        if (t + 2 < SLEN) {
            const float* src = gbase + (t + 2) * tstride;
            int nb = (t + 2) & 3;
            if (tid < 192)       cp_async4(s_qkv_a + (nb * 192 + tid) * 4, src + tid);
            else if (tid == 192) cp_async4(s_b_a + nb * 4, src + 192);
        }
        asm volatile("cp.async.commit_group;" ::: "memory");
        asm volatile("cp.async.wait_group 2;" ::: "memory");
        __syncthreads();

        // ---- phase A: v_old = W k (per-row partial over 16 cols, quad-reduce)
        float4 k0 = *(const float4*)&s_qkv[cur][64 + c0];
        float4 k1 = *(const float4*)&s_qkv[cur][64 + c0 + 4];
        float4 k2 = *(const float4*)&s_qkv[cur][64 + c0 + 8];
        float4 k3 = *(const float4*)&s_qkv[cur][64 + c0 + 12];
        float va = 0.f, vb = 0.f, vc = 0.f, vd = 0.f;
        va = fmaf(w[0], k0.x, va); vb = fmaf(w[1], k0.y, vb); vc = fmaf(w[2], k0.z, vc); vd = fmaf(w[3], k0.w, vd);
        va = fmaf(w[4], k1.x, va); vb = fmaf(w[5], k1.y, vb); vc = fmaf(w[6], k1.z, vc); vd = fmaf(w[7], k1.w, vd);
        va = fmaf(w[8], k2.x, va); vb = fmaf(w[9], k2.y, vb); vc = fmaf(w[10], k2.z, vc); vd = fmaf(w[11], k2.w, vd);
        va = fmaf(w[12], k3.x, va); vb = fmaf(w[13], k3.y, vb); vc = fmaf(w[14], k3.z, vc); vd = fmaf(w[15], k3.w, vd);
        float vo = (va + vb) + (vc + vd);
        vo += __shfl_xor_sync(0xffffffffu, vo, 1);
        vo += __shfl_xor_sync(0xffffffffu, vo, 2);

        float vi   = s_qkv[cur][128 + i];
        float beta = s_b[cur];
        float upd  = beta * (vi - vo);

        // ---- phase B: W += upd k^T ; o = W_new q (fused)
        float4 q0 = *(const float4*)&s_qkv[cur][c0];
        float4 q1 = *(const float4*)&s_qkv[cur][c0 + 4];
        float4 q2 = *(const float4*)&s_qkv[cur][c0 + 8];
        float4 q3 = *(const float4*)&s_qkv[cur][c0 + 12];
        float oa = 0.f, ob = 0.f, oc = 0.f, od = 0.f;
        w[0]  = fmaf(upd, k0.x, w[0]);  oa = fmaf(w[0],  q0.x, oa);
        w[1]  = fmaf(upd, k0.y, w[1]);  ob = fmaf(w[1],  q0.y, ob);
        w[2]  = fmaf(upd, k0.z, w[2]);  oc = fmaf(w[2],  q0.z, oc);
        w[3]  = fmaf(upd, k0.w, w[3]);  od = fmaf(w[3],  q0.w, od);
        w[4]  = fmaf(upd, k1.x, w[4]);  oa = fmaf(w[4],  q1.x, oa);
        w[5]  = fmaf(upd, k1.y, w[5]);  ob = fmaf(w[5],  q1.y, ob);
        w[6]  = fmaf(upd, k1.z, w[6]);  oc = fmaf(w[6],  q1.z, oc);
        w[7]  = fmaf(upd, k1.w, w[7]);  od = fmaf(w[7],  q1.w, od);
        w[8]  = fmaf(upd, k2.x, w[8]);  oa = fmaf(w[8],  q2.x, oa);
        w[9]  = fmaf(upd, k2.y, w[9]);  ob = fmaf(w[9],  q2.y, ob);
        w[10] = fmaf(upd, k2.z, w[10]); oc = fmaf(w[10], q2.z, oc);
        w[11] = fmaf(upd, k2.w, w[11]); od = fmaf(w[11], q2.w, od);
        w[12] = fmaf(upd, k3.x, w[12]); oa = fmaf(w[12], q3.x, oa);
        w[13] = fmaf(upd, k3.y, w[13]); ob = fmaf(w[13], q3.y, ob);
        w[14] = fmaf(upd, k3.z, w[14]); oc = fmaf(w[14], q3.z, oc);
        w[15] = fmaf(upd, k3.w, w[15]); od = fmaf(w[15], q3.w, od);
        float o = (oa + ob) + (oc + od);
        o += __shfl_xor_sync(0xffffffffu, o, 1);
        o += __shfl_xor_sync(0xffffffffu, o, 2);

        if (qd == 0) {
            size_t idx = ((size_t)(t * BSZ + b)) * 512 + h * 64 + i;
            bf16 hv = __float2bfloat16_rn(o);
            g_A2h[idx] = hv;
            g_A2l[idx] = __float2bfloat16_rn(o - __bfloat162float(hv));
        }
        __syncthreads();  // all reads of 'cur' done before it is overwritten at t+2
    }
}

// ------------------------------------------------------------------ launch
extern "C" void kernel_launch(void* const* d_in, const int* in_sizes, int n_in,
                              void* d_out, int out_size) {
    const float* x     = (const float*)d_in[0];
    const float* gamma = (const float*)d_in[1];
    const float* lnb   = (const float*)d_in[2];
    const float* wslow = (const float*)d_in[3];
    const float* wout  = (const float*)d_in[4];
    float* out = (float*)d_out;

    cudaFuncSetAttribute(gemm_kernel, cudaFuncAttributeMaxDynamicSharedMemorySize, SMEM_DYN);

    bf16 *A1h, *A1l, *A2h, *A2l, *B1h, *B1l, *B2h, *B2l;
    cudaGetSymbolAddress((void**)&A1h, g_A1h);
    cudaGetSymbolAddress((void**)&A1l, g_A1l);
    cudaGetSymbolAddress((void**)&A2h, g_A2h);
    cudaGetSymbolAddress((void**)&A2l, g_A2l);
    cudaGetSymbolAddress((void**)&B1h, g_B1h);
    cudaGetSymbolAddress((void**)&B1l, g_B1l);
    cudaGetSymbolAddress((void**)&B2h, g_B2h);
    cudaGetSymbolAddress((void**)&B2l, g_B2l);
    float* qkvb;
    cudaGetSymbolAddress((void**)&qkvb, g_qkvb);

    prep_x_kernel<<<ROWS, 128>>>(x, gamma, lnb, A1h, A1l);
    prep_b_kernel<<<dim3(NPAD1 / 32, 16), 256>>>(wslow, B1h, B1l, NQKVB);
    prep_b_kernel<<<dim3(512 / 32, 16), 256>>>(wout, B2h, B2l, 512);
    gemm_kernel<<<dim3(NT1, 256), 256, SMEM_DYN>>>(A1h, A1l, B1h, B1l, qkvb, nullptr, NQKVB);
    act_kernel<<<ROWS, 256>>>();
    scan_kernel<<<BSZ * NH, 256>>>();
    gemm_kernel<<<dim3(NT2, 256), 256, SMEM_DYN>>>(A2h, A2l, B2h, B2l, out, x, 512);
}